// round 13
// baseline (speedup 1.0000x reference)
#include <cuda_runtime.h>
#include <cuda_fp16.h>
#include <cstdint>
#include <math.h>

typedef unsigned long long u64;

#define SA_N  8192
#define SA_D  1024
#define SA_DH 128
#define BM 64
#define BN 64
#define NCU 16                  // chunks per unit (16 x 64 keys = 1024 keys)
#define NUNITS 1024             // 128 rowblocks x 8 key-eighths
#define NPART 16                // 8 eighths x 2 groups

__device__ __align__(16) __half g_qh[SA_N*SA_DH];
__device__ __align__(16) __half g_ql[SA_N*SA_DH];
__device__ __align__(16) __half g_kh[SA_N*SA_DH];
__device__ __align__(16) __half g_kl[SA_N*SA_DH];
__device__ __align__(16) __half g_v [SA_N*SA_DH];
__device__ __align__(16) __half g_xh[SA_N*SA_D];
__device__ __align__(16) __half g_xl[SA_N*SA_D];
__device__ __align__(16) __half g_wh[3*SA_D*SA_DH];
__device__ __align__(16) __half g_wl[3*SA_D*SA_DH];
__device__ float g_m16[NPART*SA_N];
__device__ float g_l16[NPART*SA_N];
__device__ float g_opart[(size_t)NPART*SA_N*SA_DH];

// attn smem: Qhi 16K | Qlo 16K | ring 4 x 48K {Khi 16K, Klo 16K, V 16K}
#define SQH 0
#define SQL 16384
#define SRING 32768
#define SLOT 49152
#define SMEM_BYTES (SRING + 4*SLOT)     // 229376 (<= 232448 opt-in)

#define SWZ(r, ch)  ((uint32_t)((r)*256 + ((((ch) ^ ((r)&7)))<<4)))
#define SWZ8(r, ch) ((uint32_t)((r)*128 + ((((ch) ^ ((r)&7)))<<4)))

__device__ __forceinline__ uint32_t smem_u32(const void* p) {
    uint32_t a;
    asm("{ .reg .u64 t; cvta.to.shared.u64 t, %1; cvt.u32.u64 %0, t; }" : "=r"(a) : "l"(p));
    return a;
}
__device__ __forceinline__ void cp_async16(uint32_t dst, const void* src) {
    asm volatile("cp.async.cg.shared.global [%0], [%1], 16;\n" :: "r"(dst), "l"(src));
}
__device__ __forceinline__ void cp_commit() { asm volatile("cp.async.commit_group;\n" ::); }
__device__ __forceinline__ void cp_wait0() { asm volatile("cp.async.wait_group 0;\n" ::); }
__device__ __forceinline__ void cp_wait1() { asm volatile("cp.async.wait_group 1;\n" ::); }

__device__ __forceinline__ void ldmx4(uint32_t a, uint32_t r[4]) {
    asm volatile("ldmatrix.sync.aligned.m8n8.x4.shared.b16 {%0,%1,%2,%3}, [%4];"
        : "=r"(r[0]), "=r"(r[1]), "=r"(r[2]), "=r"(r[3]) : "r"(a));
}
__device__ __forceinline__ void ldmx4t(uint32_t a, uint32_t r[4]) {
    asm volatile("ldmatrix.sync.aligned.m8n8.x4.trans.shared.b16 {%0,%1,%2,%3}, [%4];"
        : "=r"(r[0]), "=r"(r[1]), "=r"(r[2]), "=r"(r[3]) : "r"(a));
}
__device__ __forceinline__ void mma16816(float c[4], const uint32_t a[4],
                                         uint32_t b0, uint32_t b1) {
    asm volatile("mma.sync.aligned.m16n8k16.row.col.f32.f16.f16.f32 "
        "{%0,%1,%2,%3}, {%4,%5,%6,%7}, {%8,%9}, {%0,%1,%2,%3};"
        : "+f"(c[0]), "+f"(c[1]), "+f"(c[2]), "+f"(c[3])
        : "r"(a[0]), "r"(a[1]), "r"(a[2]), "r"(a[3]), "r"(b0), "r"(b1));
}
__device__ __forceinline__ float ex2f(float x) {
    float r; asm("ex2.approx.ftz.f32 %0, %1;" : "=f"(r) : "f"(x)); return r;
}
__device__ __forceinline__ uint32_t f16x2(float hi, float lo) {
    uint32_t d; asm("cvt.rn.f16x2.f32 %0, %1, %2;" : "=r"(d) : "f"(hi), "f"(lo)); return d;
}
__device__ __forceinline__ float2 h2f2(uint32_t d) {
    __half2 h = *(__half2*)&d; return __half22float2(h);
}

// ---------------------------------------------------------------------------
// Split kernels
// ---------------------------------------------------------------------------
__global__ void split_x_kernel(const float* __restrict__ x) {
    size_t i = ((size_t)blockIdx.x * 256 + threadIdx.x) * 4;
    float4 v = *(const float4*)&x[i];
    __half h0 = __float2half_rn(v.x), h1 = __float2half_rn(v.y);
    __half h2 = __float2half_rn(v.z), h3 = __float2half_rn(v.w);
    __half2 hh[2] = { __halves2half2(h0, h1), __halves2half2(h2, h3) };
    __half2 ll[2] = {
        __floats2half2_rn(v.x - __half2float(h0), v.y - __half2float(h1)),
        __floats2half2_rn(v.z - __half2float(h2), v.w - __half2float(h3)) };
    *(uint2*)&g_xh[i] = *(uint2*)hh;
    *(uint2*)&g_xl[i] = *(uint2*)ll;
}
__global__ void split_w_kernel(const float* __restrict__ Wq,
                               const float* __restrict__ Wk,
                               const float* __restrict__ Wv) {
    const float* W = (blockIdx.y == 0) ? Wq : (blockIdx.y == 1) ? Wk : Wv;
    size_t i = ((size_t)blockIdx.x * 256 + threadIdx.x) * 4;
    size_t o = (size_t)blockIdx.y * SA_D * SA_DH + i;
    float4 v = *(const float4*)&W[i];
    __half h0 = __float2half_rn(v.x), h1 = __float2half_rn(v.y);
    __half h2 = __float2half_rn(v.z), h3 = __float2half_rn(v.w);
    __half2 hh[2] = { __halves2half2(h0, h1), __halves2half2(h2, h3) };
    __half2 ll[2] = {
        __floats2half2_rn(v.x - __half2float(h0), v.y - __half2float(h1)),
        __floats2half2_rn(v.z - __half2float(h2), v.w - __half2float(h3)) };
    *(uint2*)&g_wh[o] = *(uint2*)hh;
    *(uint2*)&g_wl[o] = *(uint2*)ll;
}

// ---------------------------------------------------------------------------
// qkv gemm (fp16 split mma). grid=(128,3), block=128, 2 CTAs/SM.
// ---------------------------------------------------------------------------
#define GXH 0
#define GXL 8192
#define GWH 16384
#define GWL 32768
#define GBUF 49152
#define GSMEM (2*GBUF)

__device__ __forceinline__ void g_load_chunk(uint32_t dst, int row0, int ym, int kc, int tid) {
    const __half* wh = g_wh + (size_t)ym * SA_D * SA_DH;
    const __half* wl = g_wl + (size_t)ym * SA_D * SA_DH;
#pragma unroll
    for (int i = 0; i < 4; i++) {
        int c = tid + i * 128;
        int r = c >> 3, ch = c & 7;
        size_t src = (size_t)(row0 + r) * SA_D + kc * 64 + ch * 8;
        cp_async16(dst + GXH + SWZ8(r, ch), g_xh + src);
        cp_async16(dst + GXL + SWZ8(r, ch), g_xl + src);
    }
#pragma unroll
    for (int i = 0; i < 8; i++) {
        int c = tid + i * 128;
        int r = c >> 4, ch = c & 15;
        size_t src = (size_t)(kc * 64 + r) * SA_DH + ch * 8;
        cp_async16(dst + GWH + SWZ(r, ch), wh + src);
        cp_async16(dst + GWL + SWZ(r, ch), wl + src);
    }
}

__global__ __launch_bounds__(128, 2)
void qkv_gemm(const float* dummy) {
    extern __shared__ char smem[];
    const uint32_t sb = smem_u32(smem);
    const int tid = threadIdx.x, wid = tid >> 5, lane = tid & 31;
    const int g = lane >> 2, cq = lane & 3;
    const int row0 = blockIdx.x * BM;
    const int ym = blockIdx.y;
    const int rowa = wid * 16 + (lane & 15);
    const int chq0 = lane >> 4;
    const int quarter = lane >> 3;
    const int kj_sub = quarter >> 1;
    const int k_half = quarter & 1;
    const int rk = lane & 7;
    const int rwo = k_half * 8 + rk;

    float c[16][4];
#pragma unroll
    for (int n = 0; n < 16; n++)
#pragma unroll
        for (int i = 0; i < 4; i++) c[n][i] = 0.0f;

    g_load_chunk(sb, row0, ym, 0, tid);
    cp_commit();

    for (int kc = 0; kc < SA_D / 64; kc++) {
        cp_wait0();
        __syncthreads();
        const uint32_t buf = sb + (uint32_t)(kc & 1) * GBUF;
        if (kc + 1 < SA_D / 64) {
            g_load_chunk(sb + (uint32_t)((kc + 1) & 1) * GBUF, row0, ym, kc + 1, tid);
            cp_commit();
        }
#pragma unroll
        for (int kt = 0; kt < 4; kt++) {
            uint32_t ah[4], al[4];
            ldmx4(buf + GXH + SWZ8(rowa, kt * 2 + chq0), ah);
            ldmx4(buf + GXL + SWZ8(rowa, kt * 2 + chq0), al);
#pragma unroll
            for (int np = 0; np < 8; np++) {
                uint32_t bh[4], bl[4];
                uint32_t off = SWZ(kt * 16 + rwo, 2 * np + kj_sub);
                ldmx4t(buf + GWH + off, bh);
                ldmx4t(buf + GWL + off, bl);
                mma16816(c[2 * np],     ah, bh[0], bh[1]);
                mma16816(c[2 * np + 1], ah, bh[2], bh[3]);
                mma16816(c[2 * np],     ah, bl[0], bl[1]);
                mma16816(c[2 * np + 1], ah, bl[2], bl[3]);
                mma16816(c[2 * np],     al, bh[0], bh[1]);
                mma16816(c[2 * np + 1], al, bh[2], bh[3]);
            }
        }
    }

    const float qscale = (float)(1.4426950408889634 / 11.313708498984761);
    const int ra = row0 + wid * 16 + g, rb = ra + 8;
#pragma unroll
    for (int n = 0; n < 16; n++) {
        int col = n * 8 + cq * 2;
#pragma unroll
        for (int e = 0; e < 2; e++) {
            int row = e ? rb : ra;
            float v0 = e ? c[n][2] : c[n][0];
            float v1 = e ? c[n][3] : c[n][1];
            size_t idx = (size_t)row * SA_DH + col;
            if (ym == 0) {
                v0 *= qscale; v1 *= qscale;
                __half h0 = __float2half_rn(v0), h1 = __float2half_rn(v1);
                *(__half2*)&g_qh[idx] = __halves2half2(h0, h1);
                *(__half2*)&g_ql[idx] = __floats2half2_rn(v0 - __half2float(h0),
                                                          v1 - __half2float(h1));
            } else if (ym == 1) {
                __half h0 = __float2half_rn(v0), h1 = __float2half_rn(v1);
                *(__half2*)&g_kh[idx] = __halves2half2(h0, h1);
                *(__half2*)&g_kl[idx] = __floats2half2_rn(v0 - __half2float(h0),
                                                          v1 - __half2float(h1));
            } else {
                *(__half2*)&g_v[idx] = __floats2half2_rn(v0, v1);
            }
        }
    }
}

// ---------------------------------------------------------------------------
// Persistent fused flash attention. grid=148, block=256 (8 warps, 2 groups).
// 1024 units = (rowblk64, key-eighth 1024). 4-slot smem ring, 1 bar/iter.
// ---------------------------------------------------------------------------
__device__ __forceinline__ void load_chunk(uint32_t dst, size_t keybase, int tid) {
#pragma unroll
    for (int i = 0; i < 4; i++) {
        int c = tid + i * 256;
        int r = c >> 4, ch = c & 15;
        uint32_t off = SWZ(r, ch);
        size_t src = keybase + (size_t)r * SA_DH + ch * 8;
        cp_async16(dst + off,         g_kh + src);
        cp_async16(dst + 16384 + off, g_kl + src);
        cp_async16(dst + 32768 + off, g_v  + src);
    }
}

__global__ __launch_bounds__(256, 1)
void attn_kernel() {
    extern __shared__ char smem[];
    const uint32_t sb = smem_u32(smem);
    const int tid = threadIdx.x, wid = tid >> 5, lane = tid & 31;
    const int g = lane >> 2, cq = lane & 3;
    const int wg = wid & 3, group = wid >> 2;
    const int kb = group * 32;
    const int wm0 = wg * 16;

    const int rowq = wm0 + (lane & 15);
    const int chq0 = lane >> 4;
    const int quarter = lane >> 3;
    const int kj_sub = quarter >> 1;
    const int k_half = quarter & 1;
    const int rk = lane & 7;
    const int rvo = k_half * 8 + rk;

    const uint32_t ring = sb + SRING;

    auto compute_S = [&](uint32_t buf, float (*c)[4]) {
#pragma unroll
        for (int j = 0; j < 4; j++)
#pragma unroll
            for (int i = 0; i < 4; i++) c[j][i] = 0.0f;
#pragma unroll
        for (int kt = 0; kt < 8; kt++) {
            uint32_t ah[4], al[4];
            ldmx4(sb + SQH + SWZ(rowq, kt * 2 + chq0), ah);
            ldmx4(sb + SQL + SWZ(rowq, kt * 2 + chq0), al);
            uint32_t bh[2][4], bl[2][4];
#pragma unroll
            for (int np = 0; np < 2; np++) {
                int j = np * 2 + kj_sub;
                uint32_t off = SWZ(kb + j * 8 + rk, kt * 2 + k_half);
                ldmx4(buf + off, bh[np]);
                ldmx4(buf + 16384 + off, bl[np]);
            }
#pragma unroll
            for (int np = 0; np < 2; np++) {
                mma16816(c[2 * np],     ah, bh[np][0], bh[np][1]);
                mma16816(c[2 * np + 1], ah, bh[np][2], bh[np][3]);
                mma16816(c[2 * np],     ah, bl[np][0], bl[np][1]);
                mma16816(c[2 * np + 1], ah, bl[np][2], bl[np][3]);
                mma16816(c[2 * np],     al, bh[np][0], bh[np][1]);
                mma16816(c[2 * np + 1], al, bh[np][2], bh[np][3]);
            }
        }
    };

    for (int u = blockIdx.x; u < NUNITS; u += 148) {
        const int row0 = (u >> 3) * BM;
        const size_t key0 = (size_t)(u & 7) * 1024 * SA_DH;

        // ----- unit prologue: Q + chunks 0,1 -----
        {
            const __half* qh = g_qh + (size_t)row0 * SA_DH;
            const __half* ql = g_ql + (size_t)row0 * SA_DH;
#pragma unroll
            for (int i = 0; i < 4; i++) {
                int c = tid + i * 256;
                int r = c >> 4, ch = c & 15;
                uint32_t off = SWZ(r, ch);
                size_t src = (size_t)r * SA_DH + ch * 8;
                cp_async16(sb + SQH + off, qh + src);
                cp_async16(sb + SQL + off, ql + src);
            }
            load_chunk(ring, key0, tid);
            cp_commit();
            load_chunk(ring + SLOT, key0 + (size_t)BN * SA_DH, tid);
            cp_commit();
        }
        cp_wait1();
        __syncthreads();

        float o[16][4];
#pragma unroll
        for (int n = 0; n < 16; n++)
#pragma unroll
            for (int i = 0; i < 4; i++) o[n][i] = 0.0f;
        float m0 = -1e30f, m1 = -1e30f, l0 = 0.0f, l1 = 0.0f;
        float cbuf[2][4][4];
        uint32_t pp[8];

        compute_S(ring, cbuf[0]);     // S(0)

        for (int t = 0; t < NCU; t++) {
            // prefetch t+2 into slot (t+2)&3 (last read at unit-iter t-2: safe
            // pre-barrier with a 4-deep ring), keep exactly 1 group in flight.
            if (t + 2 < NCU) {
                load_chunk(ring + (uint32_t)((t + 2) & 3) * SLOT,
                           key0 + (size_t)(t + 2) * BN * SA_DH, tid);
                cp_commit();
                cp_wait1();       // chunk t+1 resident; t+2 still in flight
            } else {
                cp_wait0();
            }
            __syncthreads();      // publish chunk t+1; all warps done iter t-1

            // S(t+1) issued before softmax(t): tensor queue stays full
            if (t + 1 < NCU)
                compute_S(ring + (uint32_t)((t + 1) & 3) * SLOT, cbuf[(t + 1) & 1]);

            float (*c)[4] = cbuf[t & 1];

            // ----- online softmax on S(t) -----
            float mx0 = -1e30f, mx1 = -1e30f;
#pragma unroll
            for (int j = 0; j < 4; j++) {
                mx0 = fmaxf(mx0, fmaxf(c[j][0], c[j][1]));
                mx1 = fmaxf(mx1, fmaxf(c[j][2], c[j][3]));
            }
            mx0 = fmaxf(mx0, __shfl_xor_sync(0xffffffffu, mx0, 1));
            mx0 = fmaxf(mx0, __shfl_xor_sync(0xffffffffu, mx0, 2));
            mx1 = fmaxf(mx1, __shfl_xor_sync(0xffffffffu, mx1, 1));
            mx1 = fmaxf(mx1, __shfl_xor_sync(0xffffffffu, mx1, 2));
            float nm0 = fmaxf(m0, mx0), nm1 = fmaxf(m1, mx1);
            unsigned vote = __ballot_sync(0xffffffffu, (nm0 > m0) || (nm1 > m1));
            if (vote) {
                float a0 = ex2f(m0 - nm0), a1 = ex2f(m1 - nm1);
                m0 = nm0; m1 = nm1;
                l0 *= a0; l1 *= a1;
#pragma unroll
                for (int n = 0; n < 16; n++) {
                    o[n][0] *= a0; o[n][1] *= a0;
                    o[n][2] *= a1; o[n][3] *= a1;
                }
            }
#pragma unroll
            for (int j = 0; j < 4; j++) {
                float p0 = ex2f(c[j][0] - m0), p1 = ex2f(c[j][1] - m0);
                uint32_t pg = f16x2(p1, p0);
                float2 fb = h2f2(pg); l0 += fb.x + fb.y;
                pp[j * 2] = pg;
                float p2 = ex2f(c[j][2] - m1), p3 = ex2f(c[j][3] - m1);
                uint32_t ph = f16x2(p3, p2);
                float2 fc = h2f2(ph); l1 += fc.x + fc.y;
                pp[j * 2 + 1] = ph;
            }

            // ----- O += P V from slot t -----
            const uint32_t vbuf = ring + (uint32_t)(t & 3) * SLOT + 32768;
#pragma unroll
            for (int kt = 0; kt < 2; kt++) {
                uint32_t aP[4] = { pp[4 * kt], pp[4 * kt + 1], pp[4 * kt + 2], pp[4 * kt + 3] };
#pragma unroll
                for (int np = 0; np < 8; np++) {
                    uint32_t bv[4];
                    ldmx4t(vbuf + SWZ(kb + kt * 16 + rvo, 2 * np + kj_sub), bv);
                    mma16816(o[2 * np],     aP, bv[0], bv[1]);
                    mma16816(o[2 * np + 1], aP, bv[2], bv[3]);
                }
            }
        }

        // ----- write partials for this unit (slot = eighth*2 + group) -----
        l0 += __shfl_xor_sync(0xffffffffu, l0, 1);
        l0 += __shfl_xor_sync(0xffffffffu, l0, 2);
        l1 += __shfl_xor_sync(0xffffffffu, l1, 1);
        l1 += __shfl_xor_sync(0xffffffffu, l1, 2);

        const int s = (u & 7) * 2 + group;
        const int ra = row0 + wm0 + g, rb = ra + 8;
        if (cq == 0) {
            g_m16[s * SA_N + ra] = m0; g_l16[s * SA_N + ra] = l0;
            g_m16[s * SA_N + rb] = m1; g_l16[s * SA_N + rb] = l1;
        }
        float* oa = g_opart + ((size_t)s * SA_N + ra) * SA_DH;
        float* ob = g_opart + ((size_t)s * SA_N + rb) * SA_DH;
#pragma unroll
        for (int n = 0; n < 16; n++) {
            int col = n * 8 + cq * 2;
            *(float2*)&oa[col] = make_float2(o[n][0], o[n][1]);
            *(float2*)&ob[col] = make_float2(o[n][2], o[n][3]);
        }
        __syncthreads();   // protect Q smem + ring before next unit's loads
    }
}

// ---------------------------------------------------------------------------
__global__ void combine_kernel(float* __restrict__ out) {
    int i = blockIdx.x * 256 + threadIdx.x;         // float4 index
    int row = i >> 5;
    float mg = -1e30f;
#pragma unroll
    for (int s = 0; s < NPART; s++) mg = fmaxf(mg, g_m16[s * SA_N + row]);
    float a[NPART];
    float lsum = 0.0f;
#pragma unroll
    for (int s = 0; s < NPART; s++) {
        a[s] = ex2f(g_m16[s * SA_N + row] - mg);
        lsum += g_l16[s * SA_N + row] * a[s];
    }
    float inv = 1.0f / lsum;
    float4 acc = make_float4(0.f, 0.f, 0.f, 0.f);
#pragma unroll
    for (int s = 0; s < NPART; s++) {
        float4 p = *(const float4*)&g_opart[(size_t)s * SA_N * SA_DH + (size_t)i * 4];
        acc.x += p.x * a[s]; acc.y += p.y * a[s];
        acc.z += p.z * a[s]; acc.w += p.w * a[s];
    }
    acc.x *= inv; acc.y *= inv; acc.z *= inv; acc.w *= inv;
    *(float4*)&out[(size_t)i * 4] = acc;
}

// ---------------------------------------------------------------------------
extern "C" void kernel_launch(void* const* d_in, const int* in_sizes, int n_in,
                              void* d_out, int out_size) {
    const float* x  = (const float*)d_in[0];
    const float* Wq = (const float*)d_in[1];
    const float* Wk = (const float*)d_in[2];
    const float* Wv = (const float*)d_in[3];
    float* out = (float*)d_out;

    cudaFuncSetAttribute(attn_kernel, cudaFuncAttributeMaxDynamicSharedMemorySize, SMEM_BYTES);
    cudaFuncSetAttribute(qkv_gemm, cudaFuncAttributeMaxDynamicSharedMemorySize, GSMEM);

    split_x_kernel<<<SA_N * SA_D / 4 / 256, 256>>>(x);
    split_w_kernel<<<dim3(SA_D * SA_DH / 4 / 256, 3), 256>>>(Wq, Wk, Wv);
    qkv_gemm<<<dim3(SA_N / BM, 3), 128, GSMEM>>>(nullptr);
    attn_kernel<<<148, 256, SMEM_BYTES>>>();
    combine_kernel<<<SA_N * SA_DH / 4 / 256, 256>>>(out);
}

// round 14
// speedup vs baseline: 1.4818x; 1.4818x over previous
#include <cuda_runtime.h>
#include <cuda_fp16.h>
#include <cstdint>
#include <math.h>

typedef unsigned long long u64;

#define SA_N  8192
#define SA_D  1024
#define SA_DH 128
#define BM 64
#define BN 64
#define NC (SA_N/BN)

__device__ __align__(16) __half g_qh[SA_N*SA_DH];
__device__ __align__(16) __half g_ql[SA_N*SA_DH];
__device__ __align__(16) __half g_kh[SA_N*SA_DH];
__device__ __align__(16) __half g_kl[SA_N*SA_DH];
__device__ __align__(16) __half g_v [SA_N*SA_DH];
__device__ __align__(16) __half g_xh[SA_N*SA_D];
__device__ __align__(16) __half g_xl[SA_N*SA_D];
__device__ __align__(16) __half g_wh[3*SA_D*SA_DH];
__device__ __align__(16) __half g_wl[3*SA_D*SA_DH];

// attn smem: Qhi 16K | Qlo 16K | ring 4 x 48K {Khi 16K, Klo 16K, V 16K}
#define SQH 0
#define SQL 16384
#define SBUF 32768
#define BUFSZ 49152
#define SMEM_BYTES (SBUF + 4*BUFSZ)   // 229376

#define SWZ(r, ch)  ((uint32_t)((r)*256 + ((((ch) ^ ((r)&7)))<<4)))
#define SWZ8(r, ch) ((uint32_t)((r)*128 + ((((ch) ^ ((r)&7)))<<4)))

__device__ __forceinline__ uint32_t smem_u32(const void* p) {
    uint32_t a;
    asm("{ .reg .u64 t; cvta.to.shared.u64 t, %1; cvt.u32.u64 %0, t; }" : "=r"(a) : "l"(p));
    return a;
}
__device__ __forceinline__ void cp_async16(uint32_t dst, const void* src) {
    asm volatile("cp.async.cg.shared.global [%0], [%1], 16;\n" :: "r"(dst), "l"(src));
}
__device__ __forceinline__ void cp_commit() { asm volatile("cp.async.commit_group;\n" ::); }
__device__ __forceinline__ void cp_wait0() { asm volatile("cp.async.wait_group 0;\n" ::); }
__device__ __forceinline__ void cp_wait1() { asm volatile("cp.async.wait_group 1;\n" ::); }

__device__ __forceinline__ void ldmx4(uint32_t a, uint32_t r[4]) {
    asm volatile("ldmatrix.sync.aligned.m8n8.x4.shared.b16 {%0,%1,%2,%3}, [%4];"
        : "=r"(r[0]), "=r"(r[1]), "=r"(r[2]), "=r"(r[3]) : "r"(a));
}
__device__ __forceinline__ void ldmx4t(uint32_t a, uint32_t r[4]) {
    asm volatile("ldmatrix.sync.aligned.m8n8.x4.trans.shared.b16 {%0,%1,%2,%3}, [%4];"
        : "=r"(r[0]), "=r"(r[1]), "=r"(r[2]), "=r"(r[3]) : "r"(a));
}
__device__ __forceinline__ void mma16816(float c[4], const uint32_t a[4],
                                         uint32_t b0, uint32_t b1) {
    asm volatile("mma.sync.aligned.m16n8k16.row.col.f32.f16.f16.f32 "
        "{%0,%1,%2,%3}, {%4,%5,%6,%7}, {%8,%9}, {%0,%1,%2,%3};"
        : "+f"(c[0]), "+f"(c[1]), "+f"(c[2]), "+f"(c[3])
        : "r"(a[0]), "r"(a[1]), "r"(a[2]), "r"(a[3]), "r"(b0), "r"(b1));
}
__device__ __forceinline__ float ex2f(float x) {
    float r; asm("ex2.approx.ftz.f32 %0, %1;" : "=f"(r) : "f"(x)); return r;
}
__device__ __forceinline__ uint32_t f16x2(float hi, float lo) {
    uint32_t d; asm("cvt.rn.f16x2.f32 %0, %1, %2;" : "=r"(d) : "f"(hi), "f"(lo)); return d;
}
__device__ __forceinline__ float2 h2f2(uint32_t d) {
    __half2 h = *(__half2*)&d; return __half22float2(h);
}

// ---------------------------------------------------------------------------
// Split kernels
// ---------------------------------------------------------------------------
__global__ void split_x_kernel(const float* __restrict__ x) {
    size_t i = ((size_t)blockIdx.x * 256 + threadIdx.x) * 4;
    float4 v = *(const float4*)&x[i];
    __half h0 = __float2half_rn(v.x), h1 = __float2half_rn(v.y);
    __half h2 = __float2half_rn(v.z), h3 = __float2half_rn(v.w);
    __half2 hh[2] = { __halves2half2(h0, h1), __halves2half2(h2, h3) };
    __half2 ll[2] = {
        __floats2half2_rn(v.x - __half2float(h0), v.y - __half2float(h1)),
        __floats2half2_rn(v.z - __half2float(h2), v.w - __half2float(h3)) };
    *(uint2*)&g_xh[i] = *(uint2*)hh;
    *(uint2*)&g_xl[i] = *(uint2*)ll;
}
__global__ void split_w_kernel(const float* __restrict__ Wq,
                               const float* __restrict__ Wk,
                               const float* __restrict__ Wv) {
    const float* W = (blockIdx.y == 0) ? Wq : (blockIdx.y == 1) ? Wk : Wv;
    size_t i = ((size_t)blockIdx.x * 256 + threadIdx.x) * 4;
    size_t o = (size_t)blockIdx.y * SA_D * SA_DH + i;
    float4 v = *(const float4*)&W[i];
    __half h0 = __float2half_rn(v.x), h1 = __float2half_rn(v.y);
    __half h2 = __float2half_rn(v.z), h3 = __float2half_rn(v.w);
    __half2 hh[2] = { __halves2half2(h0, h1), __halves2half2(h2, h3) };
    __half2 ll[2] = {
        __floats2half2_rn(v.x - __half2float(h0), v.y - __half2float(h1)),
        __floats2half2_rn(v.z - __half2float(h2), v.w - __half2float(h3)) };
    *(uint2*)&g_wh[o] = *(uint2*)hh;
    *(uint2*)&g_wl[o] = *(uint2*)ll;
}

// ---------------------------------------------------------------------------
// qkv gemm, BK=32, 3 CTAs/SM (single wave). grid=(128,3), block=128.
// smem per buf: Xh 8K | Xl 8K | Wh 8K | Wl 8K = 32K, x2 = 64K.
// ---------------------------------------------------------------------------
#define GXH 0
#define GXL 8192
#define GWH 16384
#define GWL 24576
#define GBUF 32768
#define GSMEM (2*GBUF)

__device__ __forceinline__ void g_load_chunk(uint32_t dst, int row0, int ym, int kc, int tid) {
    const __half* wh = g_wh + (size_t)ym * SA_D * SA_DH;
    const __half* wl = g_wl + (size_t)ym * SA_D * SA_DH;
    // X: 64 rows x 32 fp16 (4 chunks of 16B), stored in 128B rows (chunks 0..3)
#pragma unroll
    for (int i = 0; i < 2; i++) {
        int c = tid + i * 128;
        int r = c >> 2, ch = c & 3;
        size_t src = (size_t)(row0 + r) * SA_D + kc * 32 + ch * 8;
        cp_async16(dst + GXH + SWZ8(r, ch), g_xh + src);
        cp_async16(dst + GXL + SWZ8(r, ch), g_xl + src);
    }
    // W: 32 k-rows x 128 fp16 (16 chunks), 256B rows
#pragma unroll
    for (int i = 0; i < 4; i++) {
        int c = tid + i * 128;
        int r = c >> 4, ch = c & 15;
        size_t src = (size_t)(kc * 32 + r) * SA_DH + ch * 8;
        cp_async16(dst + GWH + SWZ(r, ch), wh + src);
        cp_async16(dst + GWL + SWZ(r, ch), wl + src);
    }
}

__global__ __launch_bounds__(128, 3)
void qkv_gemm(const float* dummy) {
    extern __shared__ char smem[];
    const uint32_t sb = smem_u32(smem);
    const int tid = threadIdx.x, wid = tid >> 5, lane = tid & 31;
    const int g = lane >> 2, cq = lane & 3;
    const int row0 = blockIdx.x * BM;
    const int ym = blockIdx.y;
    const int rowa = wid * 16 + (lane & 15);
    const int chq0 = lane >> 4;
    const int quarter = lane >> 3;
    const int kj_sub = quarter >> 1;
    const int k_half = quarter & 1;
    const int rk = lane & 7;
    const int rwo = k_half * 8 + rk;

    float c[16][4];
#pragma unroll
    for (int n = 0; n < 16; n++)
#pragma unroll
        for (int i = 0; i < 4; i++) c[n][i] = 0.0f;

    g_load_chunk(sb, row0, ym, 0, tid);
    cp_commit();

    for (int kc = 0; kc < SA_D / 32; kc++) {
        cp_wait0();
        __syncthreads();
        const uint32_t buf = sb + (uint32_t)(kc & 1) * GBUF;
        if (kc + 1 < SA_D / 32) {
            g_load_chunk(sb + (uint32_t)((kc + 1) & 1) * GBUF, row0, ym, kc + 1, tid);
            cp_commit();
        }
#pragma unroll
        for (int kt = 0; kt < 2; kt++) {
            uint32_t ah[4], al[4];
            ldmx4(buf + GXH + SWZ8(rowa, kt * 2 + chq0), ah);
            ldmx4(buf + GXL + SWZ8(rowa, kt * 2 + chq0), al);
#pragma unroll
            for (int np = 0; np < 8; np++) {
                uint32_t bh[4], bl[4];
                uint32_t off = SWZ(kt * 16 + rwo, 2 * np + kj_sub);
                ldmx4t(buf + GWH + off, bh);
                ldmx4t(buf + GWL + off, bl);
                mma16816(c[2 * np],     ah, bh[0], bh[1]);
                mma16816(c[2 * np + 1], ah, bh[2], bh[3]);
                mma16816(c[2 * np],     ah, bl[0], bl[1]);
                mma16816(c[2 * np + 1], ah, bl[2], bl[3]);
                mma16816(c[2 * np],     al, bh[0], bh[1]);
                mma16816(c[2 * np + 1], al, bh[2], bh[3]);
            }
        }
    }

    const float qscale = (float)(1.4426950408889634 / 11.313708498984761);
    const int ra = row0 + wid * 16 + g, rb = ra + 8;
#pragma unroll
    for (int n = 0; n < 16; n++) {
        int col = n * 8 + cq * 2;
#pragma unroll
        for (int e = 0; e < 2; e++) {
            int row = e ? rb : ra;
            float v0 = e ? c[n][2] : c[n][0];
            float v1 = e ? c[n][3] : c[n][1];
            size_t idx = (size_t)row * SA_DH + col;
            if (ym == 0) {
                v0 *= qscale; v1 *= qscale;
                __half h0 = __float2half_rn(v0), h1 = __float2half_rn(v1);
                *(__half2*)&g_qh[idx] = __halves2half2(h0, h1);
                *(__half2*)&g_ql[idx] = __floats2half2_rn(v0 - __half2float(h0),
                                                          v1 - __half2float(h1));
            } else if (ym == 1) {
                __half h0 = __float2half_rn(v0), h1 = __float2half_rn(v1);
                *(__half2*)&g_kh[idx] = __halves2half2(h0, h1);
                *(__half2*)&g_kl[idx] = __floats2half2_rn(v0 - __half2float(h0),
                                                          v1 - __half2float(h1));
            } else {
                *(__half2*)&g_v[idx] = __floats2half2_rn(v0, v1);
            }
        }
    }
}

// ---------------------------------------------------------------------------
// Fused flash attention (R7 schedule + fragment double-buffering + 4-slot
// ring). grid=128, block=256 (8 warps, 2 key groups).
// ---------------------------------------------------------------------------
__device__ __forceinline__ void load_chunk(uint32_t dst, int t, int tid) {
    const size_t key0 = (size_t)t * BN * SA_DH;
#pragma unroll
    for (int i = 0; i < 4; i++) {
        int c = tid + i * 256;
        int r = c >> 4, ch = c & 15;
        uint32_t off = SWZ(r, ch);
        size_t src = key0 + (size_t)r * SA_DH + ch * 8;
        cp_async16(dst + off,         g_kh + src);
        cp_async16(dst + 16384 + off, g_kl + src);
        cp_async16(dst + 32768 + off, g_v  + src);
    }
}

__global__ __launch_bounds__(256, 1)
void attn_kernel(float* __restrict__ out) {
    extern __shared__ char smem[];
    const uint32_t sb = smem_u32(smem);
    const int tid = threadIdx.x, wid = tid >> 5, lane = tid & 31;
    const int g = lane >> 2, cq = lane & 3;
    const int wg = wid & 3, group = wid >> 2;
    const int kb = group * 32;
    const int row0 = blockIdx.x * BM;
    const int wm0 = wg * 16;

    const int rowq = wm0 + (lane & 15);
    const int chq0 = lane >> 4;
    const int quarter = lane >> 3;
    const int kj_sub = quarter >> 1;
    const int k_half = quarter & 1;
    const int rk = lane & 7;
    const int rvo = k_half * 8 + rk;

    // prologue: Q + chunks 0,1
    {
        const __half* qh = g_qh + (size_t)row0 * SA_DH;
        const __half* ql = g_ql + (size_t)row0 * SA_DH;
#pragma unroll
        for (int i = 0; i < 4; i++) {
            int c = tid + i * 256;
            int r = c >> 4, ch = c & 15;
            uint32_t off = SWZ(r, ch);
            size_t src = (size_t)r * SA_DH + ch * 8;
            cp_async16(sb + SQH + off, qh + src);
            cp_async16(sb + SQL + off, ql + src);
        }
        load_chunk(sb + SBUF, 0, tid);
        cp_commit();
        load_chunk(sb + SBUF + BUFSZ, 1, tid);
        cp_commit();
    }
    cp_wait1();
    __syncthreads();

    // S with fragment double-buffering: load kt+1 frags while issuing kt MMAs
    auto compute_S = [&](uint32_t buf, float (*c)[4]) {
#pragma unroll
        for (int j = 0; j < 4; j++)
#pragma unroll
            for (int i = 0; i < 4; i++) c[j][i] = 0.0f;
        uint32_t ah[2][4], al[2][4], bh[2][2][4], bl[2][2][4];
        ldmx4(sb + SQH + SWZ(rowq, chq0), ah[0]);
        ldmx4(sb + SQL + SWZ(rowq, chq0), al[0]);
#pragma unroll
        for (int np = 0; np < 2; np++) {
            uint32_t off = SWZ(kb + (np * 2 + kj_sub) * 8 + rk, k_half);
            ldmx4(buf + off, bh[0][np]);
            ldmx4(buf + 16384 + off, bl[0][np]);
        }
#pragma unroll
        for (int kt = 0; kt < 8; kt++) {
            const int cur = kt & 1, nxt = cur ^ 1;
            if (kt < 7) {
                ldmx4(sb + SQH + SWZ(rowq, (kt + 1) * 2 + chq0), ah[nxt]);
                ldmx4(sb + SQL + SWZ(rowq, (kt + 1) * 2 + chq0), al[nxt]);
#pragma unroll
                for (int np = 0; np < 2; np++) {
                    uint32_t off = SWZ(kb + (np * 2 + kj_sub) * 8 + rk,
                                       (kt + 1) * 2 + k_half);
                    ldmx4(buf + off, bh[nxt][np]);
                    ldmx4(buf + 16384 + off, bl[nxt][np]);
                }
            }
#pragma unroll
            for (int np = 0; np < 2; np++) {
                mma16816(c[2 * np],     ah[cur], bh[cur][np][0], bh[cur][np][1]);
                mma16816(c[2 * np + 1], ah[cur], bh[cur][np][2], bh[cur][np][3]);
                mma16816(c[2 * np],     ah[cur], bl[cur][np][0], bl[cur][np][1]);
                mma16816(c[2 * np + 1], ah[cur], bl[cur][np][2], bl[cur][np][3]);
                mma16816(c[2 * np],     al[cur], bh[cur][np][0], bh[cur][np][1]);
                mma16816(c[2 * np + 1], al[cur], bh[cur][np][2], bh[cur][np][3]);
            }
        }
    };

    float o[16][4];
#pragma unroll
    for (int n = 0; n < 16; n++)
#pragma unroll
        for (int i = 0; i < 4; i++) o[n][i] = 0.0f;
    float m0 = -1e30f, m1 = -1e30f, l0 = 0.0f, l1 = 0.0f;
    float cbuf[2][4][4];
    uint32_t pp[8];

    compute_S(sb + SBUF, cbuf[0]);   // S(0)

    for (int t = 0; t < NC; t++) {
        // prefetch t+2 into slot (t+2)&3 (last read at iter t-2: race-free)
        if (t + 2 < NC) {
            load_chunk(sb + SBUF + (uint32_t)((t + 2) & 3) * BUFSZ, t + 2, tid);
            cp_commit();
            cp_wait1();      // chunk t+1 resident, t+2 in flight
        } else {
            cp_wait0();
        }
        __syncthreads();

        // S(t+1) before softmax(t): tensor queue stays full
        if (t + 1 < NC)
            compute_S(sb + SBUF + (uint32_t)((t + 1) & 3) * BUFSZ, cbuf[(t + 1) & 1]);

        float (*c)[4] = cbuf[t & 1];

        // ----- online softmax on S(t) -----
        float mx0 = -1e30f, mx1 = -1e30f;
#pragma unroll
        for (int j = 0; j < 4; j++) {
            mx0 = fmaxf(mx0, fmaxf(c[j][0], c[j][1]));
            mx1 = fmaxf(mx1, fmaxf(c[j][2], c[j][3]));
        }
        mx0 = fmaxf(mx0, __shfl_xor_sync(0xffffffffu, mx0, 1));
        mx0 = fmaxf(mx0, __shfl_xor_sync(0xffffffffu, mx0, 2));
        mx1 = fmaxf(mx1, __shfl_xor_sync(0xffffffffu, mx1, 1));
        mx1 = fmaxf(mx1, __shfl_xor_sync(0xffffffffu, mx1, 2));
        float nm0 = fmaxf(m0, mx0), nm1 = fmaxf(m1, mx1);
        unsigned vote = __ballot_sync(0xffffffffu, (nm0 > m0) || (nm1 > m1));
        if (vote) {
            float a0 = ex2f(m0 - nm0), a1 = ex2f(m1 - nm1);
            m0 = nm0; m1 = nm1;
            l0 *= a0; l1 *= a1;
#pragma unroll
            for (int n = 0; n < 16; n++) {
                o[n][0] *= a0; o[n][1] *= a0;
                o[n][2] *= a1; o[n][3] *= a1;
            }
        }
#pragma unroll
        for (int j = 0; j < 4; j++) {
            float p0 = ex2f(c[j][0] - m0), p1 = ex2f(c[j][1] - m0);
            uint32_t pg = f16x2(p1, p0);
            float2 fb = h2f2(pg); l0 += fb.x + fb.y;
            pp[j * 2] = pg;
            float p2 = ex2f(c[j][2] - m1), p3 = ex2f(c[j][3] - m1);
            uint32_t ph = f16x2(p3, p2);
            float2 fc = h2f2(ph); l1 += fc.x + fc.y;
            pp[j * 2 + 1] = ph;
        }

        // ----- O += P V from slot t (V fragments double-buffered) -----
        const uint32_t vbuf = sb + SBUF + (uint32_t)(t & 3) * BUFSZ + 32768;
#pragma unroll
        for (int kt = 0; kt < 2; kt++) {
            uint32_t aP[4] = { pp[4 * kt], pp[4 * kt + 1], pp[4 * kt + 2], pp[4 * kt + 3] };
            uint32_t bv[2][4];
            ldmx4t(vbuf + SWZ(kb + kt * 16 + rvo, kj_sub), bv[0]);
#pragma unroll
            for (int np = 0; np < 8; np++) {
                const int cur = np & 1;
                if (np < 7)
                    ldmx4t(vbuf + SWZ(kb + kt * 16 + rvo, 2 * (np + 1) + kj_sub),
                           bv[cur ^ 1]);
                mma16816(o[2 * np],     aP, bv[cur][0], bv[cur][1]);
                mma16816(o[2 * np + 1], aP, bv[cur][2], bv[cur][3]);
            }
        }
    }

    // ----- merge groups + write out -----
    l0 += __shfl_xor_sync(0xffffffffu, l0, 1);
    l0 += __shfl_xor_sync(0xffffffffu, l0, 2);
    l1 += __shfl_xor_sync(0xffffffffu, l1, 1);
    l1 += __shfl_xor_sync(0xffffffffu, l1, 2);
    __syncthreads();

    float* Osm = (float*)(smem + SBUF);
    float* Msm = (float*)(smem + SBUF + 64 * 132 * 4);
    float* Lsm = Msm + 64;
    const int ral = wm0 + g, rbl = ral + 8;

    if (group == 1) {
        if (cq == 0) {
            Msm[ral] = m0; Lsm[ral] = l0;
            Msm[rbl] = m1; Lsm[rbl] = l1;
        }
#pragma unroll
        for (int n = 0; n < 16; n++) {
            int col = n * 8 + cq * 2;
            *(float2*)&Osm[ral * 132 + col] = make_float2(o[n][0], o[n][1]);
            *(float2*)&Osm[rbl * 132 + col] = make_float2(o[n][2], o[n][3]);
        }
    }
    __syncthreads();
    if (group == 0) {
        float m1a = Msm[ral], l1a = Lsm[ral];
        float m1b = Msm[rbl], l1b = Lsm[rbl];
        float mma_ = fmaxf(m0, m1a), mmb = fmaxf(m1, m1b);
        float a0a = ex2f(m0 - mma_), a1a = ex2f(m1a - mma_);
        float a0b = ex2f(m1 - mmb), a1b = ex2f(m1b - mmb);
        float iva = 1.0f / (l0 * a0a + l1a * a1a);
        float ivb = 1.0f / (l1 * a0b + l1b * a1b);
        const int ra = row0 + ral, rb = row0 + rbl;
#pragma unroll
        for (int n = 0; n < 16; n++) {
            int col = n * 8 + cq * 2;
            float2 qa = *(float2*)&Osm[ral * 132 + col];
            float2 qb = *(float2*)&Osm[rbl * 132 + col];
            *(float2*)&out[(size_t)ra * SA_DH + col] =
                make_float2((o[n][0] * a0a + qa.x * a1a) * iva,
                            (o[n][1] * a0a + qa.y * a1a) * iva);
            *(float2*)&out[(size_t)rb * SA_DH + col] =
                make_float2((o[n][2] * a0b + qb.x * a1b) * ivb,
                            (o[n][3] * a0b + qb.y * a1b) * ivb);
        }
    }
}

// ---------------------------------------------------------------------------
extern "C" void kernel_launch(void* const* d_in, const int* in_sizes, int n_in,
                              void* d_out, int out_size) {
    const float* x  = (const float*)d_in[0];
    const float* Wq = (const float*)d_in[1];
    const float* Wk = (const float*)d_in[2];
    const float* Wv = (const float*)d_in[3];
    float* out = (float*)d_out;

    cudaFuncSetAttribute(attn_kernel, cudaFuncAttributeMaxDynamicSharedMemorySize, SMEM_BYTES);
    cudaFuncSetAttribute(qkv_gemm, cudaFuncAttributeMaxDynamicSharedMemorySize, GSMEM);

    split_x_kernel<<<SA_N * SA_D / 4 / 256, 256>>>(x);
    split_w_kernel<<<dim3(SA_D * SA_DH / 4 / 256, 3), 256>>>(Wq, Wk, Wv);
    qkv_gemm<<<dim3(SA_N / BM, 3), 128, GSMEM>>>(nullptr);
    attn_kernel<<<SA_N / BM, 256, SMEM_BYTES>>>(out);
}

// round 15
// speedup vs baseline: 1.7848x; 1.2045x over previous
#include <cuda_runtime.h>
#include <cuda_fp16.h>
#include <cstdint>
#include <math.h>

typedef unsigned long long u64;

#define SA_N  8192
#define SA_D  1024
#define SA_DH 128
#define BM 64
#define BN 64
#define NC (SA_N/BN)

// fp16 operands
__device__ __align__(16) __half g_qh[SA_N*SA_DH];
__device__ __align__(16) __half g_ql[SA_N*SA_DH];
__device__ __align__(16) __half g_kh[SA_N*SA_DH];
__device__ __align__(16) __half g_kl[SA_N*SA_DH];
__device__ __align__(16) __half g_v [SA_N*SA_DH];
// fp16 split inputs for qkv gemm
__device__ __align__(16) __half g_xh[SA_N*SA_D];
__device__ __align__(16) __half g_xl[SA_N*SA_D];
__device__ __align__(16) __half g_wh[3*SA_D*SA_DH];
__device__ __align__(16) __half g_wl[3*SA_D*SA_DH];

// attn smem: Qhi 16K | Qlo 16K | 3 x {Khi 16K, Klo 16K, V 16K}
#define SQH 0
#define SQL 16384
#define SBUF 32768
#define BUFSZ 49152
#define SMEM_BYTES (SBUF + 3*BUFSZ)   // 180224

#define SWZ(r, ch)  ((uint32_t)((r)*256 + ((((ch) ^ ((r)&7)))<<4)))
#define SWZ8(r, ch) ((uint32_t)((r)*128 + ((((ch) ^ ((r)&7)))<<4)))

__device__ __forceinline__ uint32_t smem_u32(const void* p) {
    uint32_t a;
    asm("{ .reg .u64 t; cvta.to.shared.u64 t, %1; cvt.u32.u64 %0, t; }" : "=r"(a) : "l"(p));
    return a;
}
__device__ __forceinline__ void cp_async16(uint32_t dst, const void* src) {
    asm volatile("cp.async.cg.shared.global [%0], [%1], 16;\n" :: "r"(dst), "l"(src));
}
__device__ __forceinline__ void cp_commit() { asm volatile("cp.async.commit_group;\n" ::); }
__device__ __forceinline__ void cp_waitg(int n) {
    if (n == 0) asm volatile("cp.async.wait_group 0;\n" ::);
    else        asm volatile("cp.async.wait_group 1;\n" ::);
}

__device__ __forceinline__ void ldmx4(uint32_t a, uint32_t r[4]) {
    asm volatile("ldmatrix.sync.aligned.m8n8.x4.shared.b16 {%0,%1,%2,%3}, [%4];"
        : "=r"(r[0]), "=r"(r[1]), "=r"(r[2]), "=r"(r[3]) : "r"(a));
}
__device__ __forceinline__ void ldmx4t(uint32_t a, uint32_t r[4]) {
    asm volatile("ldmatrix.sync.aligned.m8n8.x4.trans.shared.b16 {%0,%1,%2,%3}, [%4];"
        : "=r"(r[0]), "=r"(r[1]), "=r"(r[2]), "=r"(r[3]) : "r"(a));
}
__device__ __forceinline__ void mma16816(float c[4], const uint32_t a[4],
                                         uint32_t b0, uint32_t b1) {
    asm volatile("mma.sync.aligned.m16n8k16.row.col.f32.f16.f16.f32 "
        "{%0,%1,%2,%3}, {%4,%5,%6,%7}, {%8,%9}, {%0,%1,%2,%3};"
        : "+f"(c[0]), "+f"(c[1]), "+f"(c[2]), "+f"(c[3])
        : "r"(a[0]), "r"(a[1]), "r"(a[2]), "r"(a[3]), "r"(b0), "r"(b1));
}
__device__ __forceinline__ float ex2f(float x) {
    float r; asm("ex2.approx.ftz.f32 %0, %1;" : "=f"(r) : "f"(x)); return r;
}
__device__ __forceinline__ uint32_t f16x2(float hi, float lo) {
    uint32_t d; asm("cvt.rn.f16x2.f32 %0, %1, %2;" : "=r"(d) : "f"(hi), "f"(lo)); return d;
}
__device__ __forceinline__ float2 h2f2(uint32_t d) {
    __half2 h = *(__half2*)&d; return __half22float2(h);
}

// ---------------------------------------------------------------------------
// Split kernels
// ---------------------------------------------------------------------------
__global__ void split_x_kernel(const float* __restrict__ x) {
    size_t i = ((size_t)blockIdx.x * 256 + threadIdx.x) * 4;
    float4 v = *(const float4*)&x[i];
    __half h0 = __float2half_rn(v.x), h1 = __float2half_rn(v.y);
    __half h2 = __float2half_rn(v.z), h3 = __float2half_rn(v.w);
    __half2 hh[2] = { __halves2half2(h0, h1), __halves2half2(h2, h3) };
    __half2 ll[2] = {
        __floats2half2_rn(v.x - __half2float(h0), v.y - __half2float(h1)),
        __floats2half2_rn(v.z - __half2float(h2), v.w - __half2float(h3)) };
    *(uint2*)&g_xh[i] = *(uint2*)hh;
    *(uint2*)&g_xl[i] = *(uint2*)ll;
}
__global__ void split_w_kernel(const float* __restrict__ Wq,
                               const float* __restrict__ Wk,
                               const float* __restrict__ Wv) {
    const float* W = (blockIdx.y == 0) ? Wq : (blockIdx.y == 1) ? Wk : Wv;
    size_t i = ((size_t)blockIdx.x * 256 + threadIdx.x) * 4;
    size_t o = (size_t)blockIdx.y * SA_D * SA_DH + i;
    float4 v = *(const float4*)&W[i];
    __half h0 = __float2half_rn(v.x), h1 = __float2half_rn(v.y);
    __half h2 = __float2half_rn(v.z), h3 = __float2half_rn(v.w);
    __half2 hh[2] = { __halves2half2(h0, h1), __halves2half2(h2, h3) };
    __half2 ll[2] = {
        __floats2half2_rn(v.x - __half2float(h0), v.y - __half2float(h1)),
        __floats2half2_rn(v.z - __half2float(h2), v.w - __half2float(h3)) };
    *(uint2*)&g_wh[o] = *(uint2*)hh;
    *(uint2*)&g_wl[o] = *(uint2*)ll;
}

// ---------------------------------------------------------------------------
// qkv gemm, BK=32, 3 CTAs/SM (single wave). grid=(128,3), block=128.
// smem per buf: Xh 8K | Xl 8K | Wh 8K | Wl 8K = 32K, x2 = 64K.
// ---------------------------------------------------------------------------
#define GXH 0
#define GXL 8192
#define GWH 16384
#define GWL 24576
#define GBUF 32768
#define GSMEM (2*GBUF)

__device__ __forceinline__ void g_load_chunk(uint32_t dst, int row0, int ym, int kc, int tid) {
    const __half* wh = g_wh + (size_t)ym * SA_D * SA_DH;
    const __half* wl = g_wl + (size_t)ym * SA_D * SA_DH;
    // X: 64 rows x 32 fp16 (4 chunks of 16B), 128B rows (chunks 0..3)
#pragma unroll
    for (int i = 0; i < 2; i++) {
        int c = tid + i * 128;
        int r = c >> 2, ch = c & 3;
        size_t src = (size_t)(row0 + r) * SA_D + kc * 32 + ch * 8;
        cp_async16(dst + GXH + SWZ8(r, ch), g_xh + src);
        cp_async16(dst + GXL + SWZ8(r, ch), g_xl + src);
    }
    // W: 32 k-rows x 128 fp16 (16 chunks), 256B rows
#pragma unroll
    for (int i = 0; i < 4; i++) {
        int c = tid + i * 128;
        int r = c >> 4, ch = c & 15;
        size_t src = (size_t)(kc * 32 + r) * SA_DH + ch * 8;
        cp_async16(dst + GWH + SWZ(r, ch), wh + src);
        cp_async16(dst + GWL + SWZ(r, ch), wl + src);
    }
}

__global__ __launch_bounds__(128, 3)
void qkv_gemm(const float* dummy) {
    extern __shared__ char smem[];
    const uint32_t sb = smem_u32(smem);
    const int tid = threadIdx.x, wid = tid >> 5, lane = tid & 31;
    const int g = lane >> 2, cq = lane & 3;
    const int row0 = blockIdx.x * BM;
    const int ym = blockIdx.y;
    const int rowa = wid * 16 + (lane & 15);
    const int chq0 = lane >> 4;
    const int quarter = lane >> 3;
    const int kj_sub = quarter >> 1;
    const int k_half = quarter & 1;
    const int rk = lane & 7;
    const int rwo = k_half * 8 + rk;

    float c[16][4];
#pragma unroll
    for (int n = 0; n < 16; n++)
#pragma unroll
        for (int i = 0; i < 4; i++) c[n][i] = 0.0f;

    g_load_chunk(sb, row0, ym, 0, tid);
    cp_commit();

    for (int kc = 0; kc < SA_D / 32; kc++) {
        cp_waitg(0);
        __syncthreads();
        const uint32_t buf = sb + (uint32_t)(kc & 1) * GBUF;
        if (kc + 1 < SA_D / 32) {
            g_load_chunk(sb + (uint32_t)((kc + 1) & 1) * GBUF, row0, ym, kc + 1, tid);
            cp_commit();
        }
#pragma unroll
        for (int kt = 0; kt < 2; kt++) {
            uint32_t ah[4], al[4];
            ldmx4(buf + GXH + SWZ8(rowa, kt * 2 + chq0), ah);
            ldmx4(buf + GXL + SWZ8(rowa, kt * 2 + chq0), al);
#pragma unroll
            for (int np = 0; np < 8; np++) {
                uint32_t bh[4], bl[4];
                uint32_t off = SWZ(kt * 16 + rwo, 2 * np + kj_sub);
                ldmx4t(buf + GWH + off, bh);
                ldmx4t(buf + GWL + off, bl);
                mma16816(c[2 * np],     ah, bh[0], bh[1]);
                mma16816(c[2 * np + 1], ah, bh[2], bh[3]);
                mma16816(c[2 * np],     ah, bl[0], bl[1]);
                mma16816(c[2 * np + 1], ah, bl[2], bl[3]);
                mma16816(c[2 * np],     al, bh[0], bh[1]);
                mma16816(c[2 * np + 1], al, bh[2], bh[3]);
            }
        }
    }

    const float qscale = (float)(1.4426950408889634 / 11.313708498984761);
    const int ra = row0 + wid * 16 + g, rb = ra + 8;
#pragma unroll
    for (int n = 0; n < 16; n++) {
        int col = n * 8 + cq * 2;
#pragma unroll
        for (int e = 0; e < 2; e++) {
            int row = e ? rb : ra;
            float v0 = e ? c[n][2] : c[n][0];
            float v1 = e ? c[n][3] : c[n][1];
            size_t idx = (size_t)row * SA_DH + col;
            if (ym == 0) {
                v0 *= qscale; v1 *= qscale;
                __half h0 = __float2half_rn(v0), h1 = __float2half_rn(v1);
                *(__half2*)&g_qh[idx] = __halves2half2(h0, h1);
                *(__half2*)&g_ql[idx] = __floats2half2_rn(v0 - __half2float(h0),
                                                          v1 - __half2float(h1));
            } else if (ym == 1) {
                __half h0 = __float2half_rn(v0), h1 = __float2half_rn(v1);
                *(__half2*)&g_kh[idx] = __halves2half2(h0, h1);
                *(__half2*)&g_kl[idx] = __floats2half2_rn(v0 - __half2float(h0),
                                                          v1 - __half2float(h1));
            } else {
                *(__half2*)&g_v[idx] = __floats2half2_rn(v0, v1);
            }
        }
    }
}

// ---------------------------------------------------------------------------
// Fused flash attention, 8 warps, pipelined S (R7 schedule). grid=128,
// block=256.
// ---------------------------------------------------------------------------
__device__ __forceinline__ void load_chunk(uint32_t dst, int t, int tid) {
    const size_t key0 = (size_t)t * BN * SA_DH;
#pragma unroll
    for (int i = 0; i < 4; i++) {
        int c = tid + i * 256;
        int r = c >> 4, ch = c & 15;
        uint32_t off = SWZ(r, ch);
        size_t src = key0 + (size_t)r * SA_DH + ch * 8;
        cp_async16(dst + off,         g_kh + src);
        cp_async16(dst + 16384 + off, g_kl + src);
        cp_async16(dst + 32768 + off, g_v  + src);
    }
}

__global__ __launch_bounds__(256, 1)
void attn_kernel(float* __restrict__ out) {
    extern __shared__ char smem[];
    const uint32_t sb = smem_u32(smem);
    const int tid = threadIdx.x, wid = tid >> 5, lane = tid & 31;
    const int g = lane >> 2, cq = lane & 3;
    const int wg = wid & 3, group = wid >> 2;
    const int kb = group * 32;
    const int row0 = blockIdx.x * BM;
    const int wm0 = wg * 16;

    const int rowq = wm0 + (lane & 15);
    const int chq0 = lane >> 4;
    const int quarter = lane >> 3;
    const int kj_sub = quarter >> 1;
    const int k_half = quarter & 1;
    const int rk = lane & 7;
    const int rvo = k_half * 8 + rk;

    // prologue: Q + chunks 0,1
    {
        const __half* qh = g_qh + (size_t)row0 * SA_DH;
        const __half* ql = g_ql + (size_t)row0 * SA_DH;
#pragma unroll
        for (int i = 0; i < 4; i++) {
            int c = tid + i * 256;
            int r = c >> 4, ch = c & 15;
            uint32_t off = SWZ(r, ch);
            size_t src = (size_t)r * SA_DH + ch * 8;
            cp_async16(sb + SQH + off, qh + src);
            cp_async16(sb + SQL + off, ql + src);
        }
        load_chunk(sb + SBUF, 0, tid);
        cp_commit();
        load_chunk(sb + SBUF + BUFSZ, 1, tid);
        cp_commit();
    }

    auto compute_S = [&](uint32_t buf, float (*c)[4]) {
#pragma unroll
        for (int j = 0; j < 4; j++)
#pragma unroll
            for (int i = 0; i < 4; i++) c[j][i] = 0.0f;
#pragma unroll
        for (int kt = 0; kt < 8; kt++) {
            uint32_t ah[4], al[4];
            ldmx4(sb + SQH + SWZ(rowq, kt * 2 + chq0), ah);
            ldmx4(sb + SQL + SWZ(rowq, kt * 2 + chq0), al);
            uint32_t bh[2][4], bl[2][4];
#pragma unroll
            for (int np = 0; np < 2; np++) {
                int j = np * 2 + kj_sub;
                uint32_t off = SWZ(kb + j * 8 + rk, kt * 2 + k_half);
                ldmx4(buf + off, bh[np]);
                ldmx4(buf + 16384 + off, bl[np]);
            }
#pragma unroll
            for (int np = 0; np < 2; np++) {
                mma16816(c[2 * np],     ah, bh[np][0], bh[np][1]);
                mma16816(c[2 * np + 1], ah, bh[np][2], bh[np][3]);
                mma16816(c[2 * np],     ah, bl[np][0], bl[np][1]);
                mma16816(c[2 * np + 1], ah, bl[np][2], bl[np][3]);
                mma16816(c[2 * np],     al, bh[np][0], bh[np][1]);
                mma16816(c[2 * np + 1], al, bh[np][2], bh[np][3]);
            }
        }
    };

    float o[16][4];
#pragma unroll
    for (int n = 0; n < 16; n++)
#pragma unroll
        for (int i = 0; i < 4; i++) o[n][i] = 0.0f;
    float m0 = -1e30f, m1 = -1e30f, l0 = 0.0f, l1 = 0.0f;

    float cbuf[2][4][4];
    uint32_t pp[8];

    // S(0)
    cp_waitg(1);
    __syncthreads();
    compute_S(sb + SBUF, cbuf[0]);

#pragma unroll 2
    for (int t = 0; t < NC; t++) {
        // prefetch t+2, ensure t+1 resident
        if (t + 2 < NC) {
            load_chunk(sb + SBUF + (uint32_t)((t + 2) % 3) * BUFSZ, t + 2, tid);
            cp_commit();
            cp_waitg(1);
        } else {
            cp_waitg(0);
        }
        __syncthreads();

        // issue S(t+1) early — fills tensor pipe under softmax(t)
        if (t + 1 < NC)
            compute_S(sb + SBUF + (uint32_t)((t + 1) % 3) * BUFSZ, cbuf[(t + 1) & 1]);

        float (*c)[4] = cbuf[t & 1];

        // ----- online softmax on S(t) -----
        float mx0 = -1e30f, mx1 = -1e30f;
#pragma unroll
        for (int j = 0; j < 4; j++) {
            mx0 = fmaxf(mx0, fmaxf(c[j][0], c[j][1]));
            mx1 = fmaxf(mx1, fmaxf(c[j][2], c[j][3]));
        }
        mx0 = fmaxf(mx0, __shfl_xor_sync(0xffffffffu, mx0, 1));
        mx0 = fmaxf(mx0, __shfl_xor_sync(0xffffffffu, mx0, 2));
        mx1 = fmaxf(mx1, __shfl_xor_sync(0xffffffffu, mx1, 1));
        mx1 = fmaxf(mx1, __shfl_xor_sync(0xffffffffu, mx1, 2));
        float nm0 = fmaxf(m0, mx0), nm1 = fmaxf(m1, mx1);
        unsigned vote = __ballot_sync(0xffffffffu, (nm0 > m0) || (nm1 > m1));
        if (vote) {
            float a0 = ex2f(m0 - nm0), a1 = ex2f(m1 - nm1);
            m0 = nm0; m1 = nm1;
            l0 *= a0; l1 *= a1;
#pragma unroll
            for (int n = 0; n < 16; n++) {
                o[n][0] *= a0; o[n][1] *= a0;
                o[n][2] *= a1; o[n][3] *= a1;
            }
        }
#pragma unroll
        for (int j = 0; j < 4; j++) {
            float p0 = ex2f(c[j][0] - m0), p1 = ex2f(c[j][1] - m0);
            uint32_t pg = f16x2(p1, p0);
            float2 fb = h2f2(pg); l0 += fb.x + fb.y;
            pp[j * 2] = pg;
            float p2 = ex2f(c[j][2] - m1), p3 = ex2f(c[j][3] - m1);
            uint32_t ph = f16x2(p3, p2);
            float2 fc = h2f2(ph); l1 += fc.x + fc.y;
            pp[j * 2 + 1] = ph;
        }

        // ----- O += P V (reads V(t) buffer) -----
        const uint32_t vbuf = sb + SBUF + (uint32_t)(t % 3) * BUFSZ + 32768;
#pragma unroll
        for (int kt = 0; kt < 2; kt++) {
            uint32_t aP[4] = { pp[4 * kt], pp[4 * kt + 1], pp[4 * kt + 2], pp[4 * kt + 3] };
#pragma unroll
            for (int np = 0; np < 8; np++) {
                uint32_t bv[4];
                ldmx4t(vbuf + SWZ(kb + kt * 16 + rvo, 2 * np + kj_sub), bv);
                mma16816(o[2 * np],     aP, bv[0], bv[1]);
                mma16816(o[2 * np + 1], aP, bv[2], bv[3]);
            }
        }
    }

    // ----- merge groups + write out -----
    l0 += __shfl_xor_sync(0xffffffffu, l0, 1);
    l0 += __shfl_xor_sync(0xffffffffu, l0, 2);
    l1 += __shfl_xor_sync(0xffffffffu, l1, 1);
    l1 += __shfl_xor_sync(0xffffffffu, l1, 2);
    __syncthreads();

    float* Osm = (float*)(smem + SBUF);
    float* Msm = (float*)(smem + SBUF + 64 * 132 * 4);
    float* Lsm = Msm + 64;
    const int ral = wm0 + g, rbl = ral + 8;

    if (group == 1) {
        if (cq == 0) {
            Msm[ral] = m0; Lsm[ral] = l0;
            Msm[rbl] = m1; Lsm[rbl] = l1;
        }
#pragma unroll
        for (int n = 0; n < 16; n++) {
            int col = n * 8 + cq * 2;
            *(float2*)&Osm[ral * 132 + col] = make_float2(o[n][0], o[n][1]);
            *(float2*)&Osm[rbl * 132 + col] = make_float2(o[n][2], o[n][3]);
        }
    }
    __syncthreads();
    if (group == 0) {
        float m1a = Msm[ral], l1a = Lsm[ral];
        float m1b = Msm[rbl], l1b = Lsm[rbl];
        float mma_ = fmaxf(m0, m1a), mmb = fmaxf(m1, m1b);
        float a0a = ex2f(m0 - mma_), a1a = ex2f(m1a - mma_);
        float a0b = ex2f(m1 - mmb), a1b = ex2f(m1b - mmb);
        float iva = 1.0f / (l0 * a0a + l1a * a1a);
        float ivb = 1.0f / (l1 * a0b + l1b * a1b);
        const int ra = row0 + ral, rb = row0 + rbl;
#pragma unroll
        for (int n = 0; n < 16; n++) {
            int col = n * 8 + cq * 2;
            float2 qa = *(float2*)&Osm[ral * 132 + col];
            float2 qb = *(float2*)&Osm[rbl * 132 + col];
            *(float2*)&out[(size_t)ra * SA_DH + col] =
                make_float2((o[n][0] * a0a + qa.x * a1a) * iva,
                            (o[n][1] * a0a + qa.y * a1a) * iva);
            *(float2*)&out[(size_t)rb * SA_DH + col] =
                make_float2((o[n][2] * a0b + qb.x * a1b) * ivb,
                            (o[n][3] * a0b + qb.y * a1b) * ivb);
        }
    }
}

// ---------------------------------------------------------------------------
extern "C" void kernel_launch(void* const* d_in, const int* in_sizes, int n_in,
                              void* d_out, int out_size) {
    const float* x  = (const float*)d_in[0];
    const float* Wq = (const float*)d_in[1];
    const float* Wk = (const float*)d_in[2];
    const float* Wv = (const float*)d_in[3];
    float* out = (float*)d_out;

    cudaFuncSetAttribute(attn_kernel, cudaFuncAttributeMaxDynamicSharedMemorySize, SMEM_BYTES);
    cudaFuncSetAttribute(qkv_gemm, cudaFuncAttributeMaxDynamicSharedMemorySize, GSMEM);

    split_x_kernel<<<SA_N * SA_D / 4 / 256, 256>>>(x);
    split_w_kernel<<<dim3(SA_D * SA_DH / 4 / 256, 3), 256>>>(Wq, Wk, Wv);
    qkv_gemm<<<dim3(SA_N / BM, 3), 128, GSMEM>>>(nullptr);
    attn_kernel<<<SA_N / BM, 256, SMEM_BYTES>>>(out);
}